// round 14
// baseline (speedup 1.0000x reference)
#include <cuda_runtime.h>
#include <cuda_bf16.h>
#include <cstdint>

#define D_MODEL 1280
#define SEQ     1024
#define N_BF    8
#define N_FR    4
#define N_HEADS 20
#define HDIM    64
#define M_TOT   (N_BF*SEQ)   // 8192

// Scratch (allocation-free rule: device globals). All bf16.
__device__ __nv_bfloat16 g_hs[(size_t)M_TOT * D_MODEL];
__device__ __nv_bfloat16 g_wq[(size_t)D_MODEL * D_MODEL];
__device__ __nv_bfloat16 g_wk[(size_t)D_MODEL * D_MODEL];
__device__ __nv_bfloat16 g_wv[(size_t)D_MODEL * D_MODEL];
__device__ __nv_bfloat16 g_wo[(size_t)D_MODEL * D_MODEL];
__device__ __nv_bfloat16 g_q[(size_t)M_TOT * D_MODEL];
__device__ __nv_bfloat16 g_k[(size_t)M_TOT * D_MODEL];
__device__ __nv_bfloat16 g_v[(size_t)M_TOT * D_MODEL];
__device__ __nv_bfloat16 g_attn[(size_t)M_TOT * D_MODEL];

__device__ __forceinline__ uint32_t packbf(float lo, float hi) {
    __nv_bfloat162 h = __floats2bfloat162_rn(lo, hi);
    return *reinterpret_cast<uint32_t*>(&h);
}

__device__ __forceinline__ void mma_bf16(float d[4], const uint32_t a[4], const uint32_t b[2]) {
    asm volatile(
        "mma.sync.aligned.m16n8k16.row.col.f32.bf16.bf16.f32 "
        "{%0,%1,%2,%3}, {%4,%5,%6,%7}, {%8,%9}, {%0,%1,%2,%3};\n"
        : "+f"(d[0]), "+f"(d[1]), "+f"(d[2]), "+f"(d[3])
        : "r"(a[0]), "r"(a[1]), "r"(a[2]), "r"(a[3]),
          "r"(b[0]), "r"(b[1]));
}

__device__ __forceinline__ void ldm_x4(uint32_t& r0, uint32_t& r1, uint32_t& r2, uint32_t& r3,
                                       const void* p) {
    uint32_t a = (uint32_t)__cvta_generic_to_shared(p);
    asm volatile("ldmatrix.sync.aligned.m8n8.x4.shared.b16 {%0,%1,%2,%3}, [%4];\n"
                 : "=r"(r0), "=r"(r1), "=r"(r2), "=r"(r3) : "r"(a));
}

__device__ __forceinline__ void ldm_x4_t(uint32_t& r0, uint32_t& r1, uint32_t& r2, uint32_t& r3,
                                         const void* p) {
    uint32_t a = (uint32_t)__cvta_generic_to_shared(p);
    asm volatile("ldmatrix.sync.aligned.m8n8.x4.trans.shared.b16 {%0,%1,%2,%3}, [%4];\n"
                 : "=r"(r0), "=r"(r1), "=r"(r2), "=r"(r3) : "r"(a));
}

__device__ __forceinline__ void cp16(void* smem, const void* gmem) {
    uint32_t s = (uint32_t)__cvta_generic_to_shared(smem);
    asm volatile("cp.async.cg.shared.global [%0], [%1], 16;\n" :: "r"(s), "l"(gmem));
}
__device__ __forceinline__ void cp_commit() { asm volatile("cp.async.commit_group;\n"); }
__device__ __forceinline__ void cp_wait0()  { asm volatile("cp.async.wait_group 0;\n"); }

// ---------------------------------------------------------------------------
// fp32 -> bf16 converter (round-12 versions)
// ---------------------------------------------------------------------------
__global__ void cvt_kernel(const float* __restrict__ in, __nv_bfloat16* __restrict__ out, int n)
{
    int i = (blockIdx.x * blockDim.x + threadIdx.x) * 4;
    if (i >= n) return;
    float4 v = *reinterpret_cast<const float4*>(in + i);
    __nv_bfloat162 lo = __floats2bfloat162_rn(v.x, v.y);
    __nv_bfloat162 hi = __floats2bfloat162_rn(v.z, v.w);
    uint2 o = make_uint2(*reinterpret_cast<uint32_t*>(&lo), *reinterpret_cast<uint32_t*>(&hi));
    *reinterpret_cast<uint2*>(out + i) = o;
}

__global__ void cvt4_kernel(const float* __restrict__ s0, const float* __restrict__ s1,
                            const float* __restrict__ s2, const float* __restrict__ s3,
                            __nv_bfloat16* __restrict__ d0, __nv_bfloat16* __restrict__ d1,
                            __nv_bfloat16* __restrict__ d2, __nv_bfloat16* __restrict__ d3,
                            int n)
{
    const float* in = (blockIdx.z == 0) ? s0 : (blockIdx.z == 1) ? s1
                    : (blockIdx.z == 2) ? s2 : s3;
    __nv_bfloat16* out = (blockIdx.z == 0) ? d0 : (blockIdx.z == 1) ? d1
                       : (blockIdx.z == 2) ? d2 : d3;
    int i = (blockIdx.x * blockDim.x + threadIdx.x) * 4;
    if (i >= n) return;
    float4 v = *reinterpret_cast<const float4*>(in + i);
    __nv_bfloat162 lo = __floats2bfloat162_rn(v.x, v.y);
    __nv_bfloat162 hi = __floats2bfloat162_rn(v.z, v.w);
    uint2 o = make_uint2(*reinterpret_cast<uint32_t*>(&lo), *reinterpret_cast<uint32_t*>(&hi));
    *reinterpret_cast<uint2*>(out + i) = o;
}

// ---------------------------------------------------------------------------
// C[M,N] = A[M,K] @ W[K,N] + bias (+ residual). All-bf16 inputs.
// Block tile 128x128, 4 warps (2x2) of 64x64. K-stage depth 64, double
// buffered: 20 stages -> 20 syncs (was 40), 64-MMA bursts per warp per stage.
// A [128][72] / B [64][136] layouts: 8-row ldmatrix phases conflict-free.
// ---------------------------------------------------------------------------
#define GK_NSTG   (D_MODEL / 64)   // 20
#define GA_ELEMS  (128 * 72)       // 9216
#define GB_ELEMS  (64 * 136)       // 8704
#define G_SMEM    ((2 * GA_ELEMS + 2 * GB_ELEMS) * 2)   // 71680 B

template<bool OUT_BF16, bool ADD_RES>
__global__ __launch_bounds__(128, 2)
void gemm_kernel(const __nv_bfloat16* __restrict__ A,
                 const __nv_bfloat16* __restrict__ W0, const __nv_bfloat16* __restrict__ W1,
                 const __nv_bfloat16* __restrict__ W2,
                 const float* __restrict__ b0, const float* __restrict__ b1,
                 const float* __restrict__ b2,
                 void* __restrict__ o0, void* __restrict__ o1, void* __restrict__ o2,
                 const float* __restrict__ res, int M, int N, int K)
{
    extern __shared__ __align__(16) char smem[];
    __nv_bfloat16* Abase = reinterpret_cast<__nv_bfloat16*>(smem);
    __nv_bfloat16* Bbase = Abase + 2 * GA_ELEMS;

    const int bm = blockIdx.y;
    const int which = blockIdx.x / 10, bn = blockIdx.x % 10;
    const __nv_bfloat16* W = (which == 0) ? W0 : (which == 1) ? W1 : W2;
    const float* bias = (which == 0) ? b0 : (which == 1) ? b1 : b2;
    void* outp = (which == 0) ? o0 : (which == 1) ? o1 : o2;

    const int tid = threadIdx.x;
    const int warp = tid >> 5, lane = tid & 31;
    const int wm = warp >> 1, wn = warp & 1;     // 2x2 warp grid, each 64x64
    const int gid = lane >> 2, tig = lane & 3;
    const int l15 = lane & 15, lhi = (lane >> 4) << 3;

    float acc[4][8][4];
    #pragma unroll
    for (int mt = 0; mt < 4; mt++)
        #pragma unroll
        for (int nt = 0; nt < 8; nt++)
            #pragma unroll
            for (int i = 0; i < 4; i++) acc[mt][nt][i] = 0.f;

    auto stage = [&](int s) {
        const int buf = s & 1;
        const int kt = s * 64;
        __nv_bfloat16* As = Abase + buf * GA_ELEMS;
        __nv_bfloat16* Bs = Bbase + buf * GB_ELEMS;
        #pragma unroll
        for (int i = 0; i < 8; i++) {       // A: 128x64 = 1024 16B-chunks
            int idx = tid + i * 128;
            int r = idx >> 3, c = (idx & 7) * 8;
            cp16(As + r * 72 + c, A + (size_t)(bm * 128 + r) * K + kt + c);
        }
        #pragma unroll
        for (int i = 0; i < 8; i++) {       // B: 64x128 = 1024 16B-chunks
            int idx = tid + i * 128;
            int r = idx >> 4, c = (idx & 15) * 8;
            cp16(Bs + r * 136 + c, W + (size_t)(kt + r) * N + bn * 128 + c);
        }
        cp_commit();
    };

    stage(0);

    for (int s = 0; s < GK_NSTG; s++) {
        cp_wait0();
        __syncthreads();
        if (s + 1 < GK_NSTG) stage(s + 1);   // overlaps compute of stage s

        const int buf = s & 1;
        const __nv_bfloat16* As = Abase + buf * GA_ELEMS;
        const __nv_bfloat16* Bs = Bbase + buf * GB_ELEMS;

        #pragma unroll
        for (int kk = 0; kk < 64; kk += 16) {
            uint32_t aA[4][4];
            #pragma unroll
            for (int mt = 0; mt < 4; mt++)
                ldm_x4(aA[mt][0], aA[mt][1], aA[mt][2], aA[mt][3],
                       As + (wm * 64 + mt * 16 + l15) * 72 + kk + lhi);
            uint32_t bB[8][2];
            #pragma unroll
            for (int nh = 0; nh < 4; nh++) {
                uint32_t t0, t1, t2, t3;
                ldm_x4_t(t0, t1, t2, t3,
                         Bs + (kk + l15) * 136 + wn * 64 + nh * 16 + lhi);
                bB[2 * nh][0] = t0; bB[2 * nh][1] = t1;
                bB[2 * nh + 1][0] = t2; bB[2 * nh + 1][1] = t3;
            }
            #pragma unroll
            for (int mt = 0; mt < 4; mt++)
                #pragma unroll
                for (int nt = 0; nt < 8; nt++)
                    mma_bf16(acc[mt][nt], aA[mt], bB[nt]);
        }
        __syncthreads();    // readers done before next stage's writers reuse buf
    }

    // Epilogue
    #pragma unroll
    for (int mt = 0; mt < 4; mt++) {
        int row = bm * 128 + wm * 64 + mt * 16 + gid;
        #pragma unroll
        for (int nt = 0; nt < 8; nt++) {
            int col = bn * 128 + wn * 64 + nt * 8 + 2 * tig;
            float bb0 = bias[col], bb1 = bias[col + 1];
            size_t i0 = (size_t)row * N + col;
            size_t i1 = i0 + 8 * (size_t)N;
            float v0 = acc[mt][nt][0] + bb0, v1 = acc[mt][nt][1] + bb1;
            float v2 = acc[mt][nt][2] + bb0, v3 = acc[mt][nt][3] + bb1;
            if (OUT_BF16) {
                __nv_bfloat16* C = (__nv_bfloat16*)outp;
                *reinterpret_cast<__nv_bfloat162*>(C + i0) = __floats2bfloat162_rn(v0, v1);
                *reinterpret_cast<__nv_bfloat162*>(C + i1) = __floats2bfloat162_rn(v2, v3);
            } else {
                float* C = (float*)outp;
                if (ADD_RES) {
                    float2 r0 = *reinterpret_cast<const float2*>(res + i0);
                    float2 r1 = *reinterpret_cast<const float2*>(res + i1);
                    v0 += r0.x; v1 += r0.y; v2 += r1.x; v3 += r1.y;
                }
                *reinterpret_cast<float2*>(C + i0) = make_float2(v0, v1);
                *reinterpret_cast<float2*>(C + i1) = make_float2(v2, v3);
            }
        }
    }
}

// ---------------------------------------------------------------------------
// Flash attention (exact round-12 best): 128-row Q tile, 4 warps x two m16
// row-groups, no-max exp2 softmax, frame-0 shortcut, 2-buffer cp.async KV.
// ---------------------------------------------------------------------------
#define AT_QROWS   128
#define AT_SMEM    ((AT_QROWS * 72 + 2 * 64 * 72 + 2 * 64 * 72) * 2)  // 55296 B

__global__ __launch_bounds__(128)
void attn_kernel()
{
    extern __shared__ __align__(16) __nv_bfloat16 sm[];
    __nv_bfloat16* Qs = sm;                       // [128][72]
    __nv_bfloat16* Kb = sm + AT_QROWS * 72;       // [2][64][72]
    __nv_bfloat16* Vb = Kb + 2 * 64 * 72;         // [2][64][72]

    const int qt = blockIdx.x, h = blockIdx.y, bfi = blockIdx.z;
    const int bf0 = bfi & ~(N_FR - 1);
    const int nt_loop = ((bfi & (N_FR - 1)) == 0) ? 16 : 32;  // frame-0 shortcut
    const int tid = threadIdx.x;
    const int w = tid >> 5, lane = tid & 31;
    const int gid = lane >> 2, tig = lane & 3;
    const int l15 = lane & 15, lhi = (lane >> 4) << 3;

    // Stage Q tile, pre-scaled by 0.125 * log2(e)
    {
        const float qsc = 0.125f * 1.44269504f;
        #pragma unroll
        for (int i = 0; i < 8; i++) {
            int idx = tid + i * 128;
            int r = idx >> 3, c = (idx & 7) * 8;
            const __nv_bfloat16* p = g_q + (size_t)(bfi * SEQ + qt * AT_QROWS + r) * D_MODEL + h * HDIM + c;
            uint4 v = *reinterpret_cast<const uint4*>(p);
            __nv_bfloat16* pe = reinterpret_cast<__nv_bfloat16*>(&v);
            #pragma unroll
            for (int j = 0; j < 8; j++)
                pe[j] = __float2bfloat16_rn(__bfloat162float(pe[j]) * qsc);
            *reinterpret_cast<uint4*>(Qs + r * 72 + c) = v;
        }
    }

    auto stageKV = [&](int buf, int t) {
        const int sbf = (t < 16) ? bf0 : bfi;
        const int k0 = (t & 15) * 64;
        #pragma unroll
        for (int i = 0; i < 4; i++) {
            int idx = tid + i * 128;
            int r = idx >> 3, c = (idx & 7) * 8;
            size_t base = (size_t)(sbf * SEQ + k0 + r) * D_MODEL + h * HDIM + c;
            cp16(Kb + buf * 4608 + r * 72 + c, g_k + base);
            cp16(Vb + buf * 4608 + r * 72 + c, g_v + base);
        }
        cp_commit();
    };

    stageKV(0, 0);
    __syncthreads();

    uint32_t qf[2][4][4];
    #pragma unroll
    for (int g = 0; g < 2; g++)
        #pragma unroll
        for (int kj = 0; kj < 4; kj++)
            ldm_x4(qf[g][kj][0], qf[g][kj][1], qf[g][kj][2], qf[g][kj][3],
                   Qs + (g * 64 + w * 16 + l15) * 72 + kj * 16 + lhi);

    float oacc[2][8][4];
    #pragma unroll
    for (int g = 0; g < 2; g++)
        #pragma unroll
        for (int nt = 0; nt < 8; nt++)
            #pragma unroll
            for (int i = 0; i < 4; i++) oacc[g][nt][i] = 0.f;
    float lpart[2][2] = {{0.f, 0.f}, {0.f, 0.f}};   // lane-local partials

    int buf = 0;
    for (int t = 0; t < nt_loop; t++) {
        cp_wait0();
        __syncthreads();
        if (t + 1 < nt_loop) stageKV(buf ^ 1, t + 1);

        // S = Q @ K^T (log2 units)
        float sacc[2][8][4];
        #pragma unroll
        for (int g = 0; g < 2; g++)
            #pragma unroll
            for (int nt = 0; nt < 8; nt++)
                #pragma unroll
                for (int i = 0; i < 4; i++) sacc[g][nt][i] = 0.f;

        #pragma unroll
        for (int ntp = 0; ntp < 4; ntp++) {
            #pragma unroll
            for (int kj = 0; kj < 4; kj++) {
                uint32_t t0, t1, t2, t3;
                ldm_x4(t0, t1, t2, t3, Kb + buf * 4608 + (ntp * 16 + l15) * 72 + kj * 16 + lhi);
                uint32_t be[2] = {t0, t2};
                uint32_t bo[2] = {t1, t3};
                #pragma unroll
                for (int g = 0; g < 2; g++) {
                    mma_bf16(sacc[g][2 * ntp],     qf[g][kj], be);
                    mma_bf16(sacc[g][2 * ntp + 1], qf[g][kj], bo);
                }
            }
        }

        // p = exp2(s); accumulate lane-local row sums (no max, no rescale)
        #pragma unroll
        for (int g = 0; g < 2; g++)
            #pragma unroll
            for (int nt = 0; nt < 8; nt++) {
                float p0 = exp2f(sacc[g][nt][0]), p1 = exp2f(sacc[g][nt][1]);
                float p2 = exp2f(sacc[g][nt][2]), p3 = exp2f(sacc[g][nt][3]);
                lpart[g][0] += p0 + p1; lpart[g][1] += p2 + p3;
                sacc[g][nt][0] = p0; sacc[g][nt][1] = p1;
                sacc[g][nt][2] = p2; sacc[g][nt][3] = p3;
            }

        // O += P @ V
        #pragma unroll
        for (int kj = 0; kj < 4; kj++) {
            uint32_t ap[2][4];
            #pragma unroll
            for (int g = 0; g < 2; g++) {
                ap[g][0] = packbf(sacc[g][2 * kj][0],     sacc[g][2 * kj][1]);
                ap[g][1] = packbf(sacc[g][2 * kj][2],     sacc[g][2 * kj][3]);
                ap[g][2] = packbf(sacc[g][2 * kj + 1][0], sacc[g][2 * kj + 1][1]);
                ap[g][3] = packbf(sacc[g][2 * kj + 1][2], sacc[g][2 * kj + 1][3]);
            }
            int vrow = kj * 16 + ((lane >> 3) & 1) * 8 + (lane & 7);
            #pragma unroll
            for (int dp = 0; dp < 4; dp++) {
                int vcol = dp * 16 + ((lane >> 4) & 1) * 8;
                uint32_t b0, b1, b2, b3;
                ldm_x4_t(b0, b1, b2, b3, Vb + buf * 4608 + vrow * 72 + vcol);
                uint32_t bb0[2] = {b0, b1};
                uint32_t bb1[2] = {b2, b3};
                #pragma unroll
                for (int g = 0; g < 2; g++) {
                    mma_bf16(oacc[g][2 * dp],     ap[g], bb0);
                    mma_bf16(oacc[g][2 * dp + 1], ap[g], bb1);
                }
            }
        }
        buf ^= 1;
    }

    // Final l reduction across the 4 lanes sharing each row (tig dimension)
    #pragma unroll
    for (int g = 0; g < 2; g++)
        #pragma unroll
        for (int j = 0; j < 2; j++) {
            lpart[g][j] += __shfl_xor_sync(0xffffffffu, lpart[g][j], 1);
            lpart[g][j] += __shfl_xor_sync(0xffffffffu, lpart[g][j], 2);
        }

    #pragma unroll
    for (int g = 0; g < 2; g++) {
        const int r0 = g * 64 + w * 16 + gid;
        const float inv0 = 1.f / lpart[g][0], inv1 = 1.f / lpart[g][1];
        #pragma unroll
        for (int nt = 0; nt < 8; nt++) {
            int dcol = h * HDIM + nt * 8 + 2 * tig;
            size_t b0 = (size_t)(bfi * SEQ + qt * AT_QROWS + r0) * D_MODEL + dcol;
            size_t b1 = b0 + 8 * (size_t)D_MODEL;
            *reinterpret_cast<__nv_bfloat162*>(g_attn + b0) =
                __floats2bfloat162_rn(oacc[g][nt][0] * inv0, oacc[g][nt][1] * inv0);
            *reinterpret_cast<__nv_bfloat162*>(g_attn + b1) =
                __floats2bfloat162_rn(oacc[g][nt][2] * inv1, oacc[g][nt][3] * inv1);
        }
    }
}

// ---------------------------------------------------------------------------

extern "C" void kernel_launch(void* const* d_in, const int* in_sizes, int n_in,
                              void* d_out, int out_size)
{
    const float* hs = (const float*)d_in[0];
    const float* Wq = (const float*)d_in[1];
    const float* Wk = (const float*)d_in[2];
    const float* Wv = (const float*)d_in[3];
    const float* Wo = (const float*)d_in[4];
    const float* bq = (const float*)d_in[5];
    const float* bk = (const float*)d_in[6];
    const float* bv = (const float*)d_in[7];
    const float* bo = (const float*)d_in[8];
    float* out = (float*)d_out;

    __nv_bfloat16 *hsb, *wqb, *wkb, *wvb, *wob, *qp, *kp, *vp, *ap;
    cudaGetSymbolAddress((void**)&hsb, g_hs);
    cudaGetSymbolAddress((void**)&wqb, g_wq);
    cudaGetSymbolAddress((void**)&wkb, g_wk);
    cudaGetSymbolAddress((void**)&wvb, g_wv);
    cudaGetSymbolAddress((void**)&wob, g_wo);
    cudaGetSymbolAddress((void**)&qp, g_q);
    cudaGetSymbolAddress((void**)&kp, g_k);
    cudaGetSymbolAddress((void**)&vp, g_v);
    cudaGetSymbolAddress((void**)&ap, g_attn);

    const int n_hs = M_TOT * D_MODEL, n_w = D_MODEL * D_MODEL;
    cvt_kernel<<<n_hs / 4 / 256, 256>>>(hs, hsb, n_hs);
    cvt4_kernel<<<dim3(n_w / 4 / 256, 1, 4), 256>>>(Wq, Wk, Wv, Wo, wqb, wkb, wvb, wob, n_w);

    cudaFuncSetAttribute((const void*)gemm_kernel<true, false>,
                         cudaFuncAttributeMaxDynamicSharedMemorySize, G_SMEM);
    cudaFuncSetAttribute((const void*)gemm_kernel<false, true>,
                         cudaFuncAttributeMaxDynamicSharedMemorySize, G_SMEM);
    cudaFuncSetAttribute((const void*)attn_kernel,
                         cudaFuncAttributeMaxDynamicSharedMemorySize, AT_SMEM);

    // Fused QKV: grid.x = 30 (3 weights x 10 n-tiles of 128)
    gemm_kernel<true, false><<<dim3(30, M_TOT / 128), 128, G_SMEM>>>(
        hsb, wqb, wkb, wvb, bq, bk, bv, qp, kp, vp, nullptr, M_TOT, D_MODEL, D_MODEL);

    attn_kernel<<<dim3(SEQ / AT_QROWS, N_HEADS, N_BF), 128, AT_SMEM>>>();

    gemm_kernel<false, true><<<dim3(10, M_TOT / 128), 128, G_SMEM>>>(
        ap, wob, wob, wob, bo, bo, bo, out, out, out, hs, M_TOT, D_MODEL, D_MODEL);
}

// round 15
// speedup vs baseline: 1.1048x; 1.1048x over previous
#include <cuda_runtime.h>
#include <cuda_bf16.h>
#include <cstdint>

#define D_MODEL 1280
#define SEQ     1024
#define N_BF    8
#define N_FR    4
#define N_HEADS 20
#define HDIM    64
#define M_TOT   (N_BF*SEQ)   // 8192

// Scratch (allocation-free rule: device globals). All bf16.
__device__ __nv_bfloat16 g_hs[(size_t)M_TOT * D_MODEL];
__device__ __nv_bfloat16 g_wq[(size_t)D_MODEL * D_MODEL];
__device__ __nv_bfloat16 g_wk[(size_t)D_MODEL * D_MODEL];
__device__ __nv_bfloat16 g_wv[(size_t)D_MODEL * D_MODEL];
__device__ __nv_bfloat16 g_wo[(size_t)D_MODEL * D_MODEL];
__device__ __nv_bfloat16 g_q[(size_t)M_TOT * D_MODEL];
__device__ __nv_bfloat16 g_k[(size_t)M_TOT * D_MODEL];
__device__ __nv_bfloat16 g_v[(size_t)M_TOT * D_MODEL];
__device__ __nv_bfloat16 g_attn[(size_t)M_TOT * D_MODEL];

__device__ __forceinline__ void mma_bf16(float d[4], const uint32_t a[4], const uint32_t b[2]) {
    asm volatile(
        "mma.sync.aligned.m16n8k16.row.col.f32.bf16.bf16.f32 "
        "{%0,%1,%2,%3}, {%4,%5,%6,%7}, {%8,%9}, {%0,%1,%2,%3};\n"
        : "+f"(d[0]), "+f"(d[1]), "+f"(d[2]), "+f"(d[3])
        : "r"(a[0]), "r"(a[1]), "r"(a[2]), "r"(a[3]),
          "r"(b[0]), "r"(b[1]));
}

__device__ __forceinline__ void ldm_x4(uint32_t& r0, uint32_t& r1, uint32_t& r2, uint32_t& r3,
                                       const void* p) {
    uint32_t a = (uint32_t)__cvta_generic_to_shared(p);
    asm volatile("ldmatrix.sync.aligned.m8n8.x4.shared.b16 {%0,%1,%2,%3}, [%4];\n"
                 : "=r"(r0), "=r"(r1), "=r"(r2), "=r"(r3) : "r"(a));
}

__device__ __forceinline__ void ldm_x4_t(uint32_t& r0, uint32_t& r1, uint32_t& r2, uint32_t& r3,
                                         const void* p) {
    uint32_t a = (uint32_t)__cvta_generic_to_shared(p);
    asm volatile("ldmatrix.sync.aligned.m8n8.x4.trans.shared.b16 {%0,%1,%2,%3}, [%4];\n"
                 : "=r"(r0), "=r"(r1), "=r"(r2), "=r"(r3) : "r"(a));
}

__device__ __forceinline__ void ldm_x2_t(uint32_t& r0, uint32_t& r1, const void* p) {
    uint32_t a = (uint32_t)__cvta_generic_to_shared(p);
    asm volatile("ldmatrix.sync.aligned.m8n8.x2.trans.shared.b16 {%0,%1}, [%2];\n"
                 : "=r"(r0), "=r"(r1) : "r"(a));
}

// pack (lo,hi) fp32 -> bf16x2 (matches __floats2bfloat162_rn(lo,hi) layout)
__device__ __forceinline__ uint32_t cvt_bf16x2(float lo, float hi) {
    uint32_t d;
    asm("cvt.rn.bf16x2.f32 %0, %1, %2;" : "=r"(d) : "f"(hi), "f"(lo));
    return d;
}

__device__ __forceinline__ uint32_t ex2_bf16x2(uint32_t a) {
    uint32_t d;
    asm("ex2.approx.ftz.bf16x2 %0, %1;" : "=r"(d) : "r"(a));
    return d;
}

__device__ __forceinline__ void cp16(void* smem, const void* gmem) {
    uint32_t s = (uint32_t)__cvta_generic_to_shared(smem);
    asm volatile("cp.async.cg.shared.global [%0], [%1], 16;\n" :: "r"(s), "l"(gmem));
}
__device__ __forceinline__ void cp_commit() { asm volatile("cp.async.commit_group;\n"); }
__device__ __forceinline__ void cp_wait0()  { asm volatile("cp.async.wait_group 0;\n"); }
__device__ __forceinline__ void cp_wait2()  { asm volatile("cp.async.wait_group 2;\n"); }

// ---------------------------------------------------------------------------
// fp32 -> bf16 converters (round-12 exact)
// ---------------------------------------------------------------------------
__global__ void cvt_kernel(const float* __restrict__ in, __nv_bfloat16* __restrict__ out, int n)
{
    int i = (blockIdx.x * blockDim.x + threadIdx.x) * 4;
    if (i >= n) return;
    float4 v = *reinterpret_cast<const float4*>(in + i);
    __nv_bfloat162 lo = __floats2bfloat162_rn(v.x, v.y);
    __nv_bfloat162 hi = __floats2bfloat162_rn(v.z, v.w);
    uint2 o = make_uint2(*reinterpret_cast<uint32_t*>(&lo), *reinterpret_cast<uint32_t*>(&hi));
    *reinterpret_cast<uint2*>(out + i) = o;
}

__global__ void cvt4_kernel(const float* __restrict__ s0, const float* __restrict__ s1,
                            const float* __restrict__ s2, const float* __restrict__ s3,
                            __nv_bfloat16* __restrict__ d0, __nv_bfloat16* __restrict__ d1,
                            __nv_bfloat16* __restrict__ d2, __nv_bfloat16* __restrict__ d3,
                            int n)
{
    const float* in = (blockIdx.z == 0) ? s0 : (blockIdx.z == 1) ? s1
                    : (blockIdx.z == 2) ? s2 : s3;
    __nv_bfloat16* out = (blockIdx.z == 0) ? d0 : (blockIdx.z == 1) ? d1
                       : (blockIdx.z == 2) ? d2 : d3;
    int i = (blockIdx.x * blockDim.x + threadIdx.x) * 4;
    if (i >= n) return;
    float4 v = *reinterpret_cast<const float4*>(in + i);
    __nv_bfloat162 lo = __floats2bfloat162_rn(v.x, v.y);
    __nv_bfloat162 hi = __floats2bfloat162_rn(v.z, v.w);
    uint2 o = make_uint2(*reinterpret_cast<uint32_t*>(&lo), *reinterpret_cast<uint32_t*>(&hi));
    *reinterpret_cast<uint2*>(out + i) = o;
}

// ---------------------------------------------------------------------------
// GEMM (round-12 exact): 128x128 block, 4 warps of 64x64, 32-deep k-stages,
// 4-stage cp.async pipeline (wait_group 2), 2 CTAs/SM.
// ---------------------------------------------------------------------------
#define GK_NSTG   (D_MODEL / 32)   // 40
#define GA_ELEMS  (128 * 40)
#define GB_ELEMS  (32 * 136)
#define G_SMEM    ((4 * GA_ELEMS + 4 * GB_ELEMS) * 2)   // 75776 B

template<bool OUT_BF16, bool ADD_RES>
__global__ __launch_bounds__(128, 2)
void gemm_kernel(const __nv_bfloat16* __restrict__ A,
                 const __nv_bfloat16* __restrict__ W0, const __nv_bfloat16* __restrict__ W1,
                 const __nv_bfloat16* __restrict__ W2,
                 const float* __restrict__ b0, const float* __restrict__ b1,
                 const float* __restrict__ b2,
                 void* __restrict__ o0, void* __restrict__ o1, void* __restrict__ o2,
                 const float* __restrict__ res, int M, int N, int K)
{
    extern __shared__ __align__(16) char smem[];
    __nv_bfloat16* Abase = reinterpret_cast<__nv_bfloat16*>(smem);
    __nv_bfloat16* Bbase = Abase + 4 * GA_ELEMS;

    const int bm = blockIdx.y;
    const int which = blockIdx.x / 10, bn = blockIdx.x % 10;
    const __nv_bfloat16* W = (which == 0) ? W0 : (which == 1) ? W1 : W2;
    const float* bias = (which == 0) ? b0 : (which == 1) ? b1 : b2;
    void* outp = (which == 0) ? o0 : (which == 1) ? o1 : o2;

    const int tid = threadIdx.x;
    const int warp = tid >> 5, lane = tid & 31;
    const int wm = warp >> 1, wn = warp & 1;     // 2x2 warp grid, each 64x64
    const int gid = lane >> 2, tig = lane & 3;
    const int l15 = lane & 15, lhi = (lane >> 4) << 3;

    float acc[4][8][4];
    #pragma unroll
    for (int mt = 0; mt < 4; mt++)
        #pragma unroll
        for (int nt = 0; nt < 8; nt++)
            #pragma unroll
            for (int i = 0; i < 4; i++) acc[mt][nt][i] = 0.f;

    auto stage = [&](int s) {
        const int buf = s & 3;
        const int kt = s * 32;
        __nv_bfloat16* As = Abase + buf * GA_ELEMS;
        __nv_bfloat16* Bs = Bbase + buf * GB_ELEMS;
        #pragma unroll
        for (int i = 0; i < 4; i++) {
            int idx = tid + i * 128;
            int r = idx >> 2, c = (idx & 3) * 8;
            cp16(As + r * 40 + c, A + (size_t)(bm * 128 + r) * K + kt + c);
        }
        #pragma unroll
        for (int i = 0; i < 4; i++) {
            int idx = tid + i * 128;
            int r = idx >> 4, c = (idx & 15) * 8;
            cp16(Bs + r * 136 + c, W + (size_t)(kt + r) * N + bn * 128 + c);
        }
        cp_commit();
    };

    stage(0); stage(1); stage(2);

    for (int s = 0; s < GK_NSTG; s++) {
        cp_wait2();
        __syncthreads();
        if (s + 3 < GK_NSTG) stage(s + 3);
        else cp_commit();

        const int buf = s & 3;
        const __nv_bfloat16* As = Abase + buf * GA_ELEMS;
        const __nv_bfloat16* Bs = Bbase + buf * GB_ELEMS;

        #pragma unroll
        for (int kk = 0; kk < 32; kk += 16) {
            uint32_t aA[4][4];
            #pragma unroll
            for (int mt = 0; mt < 4; mt++)
                ldm_x4(aA[mt][0], aA[mt][1], aA[mt][2], aA[mt][3],
                       As + (wm * 64 + mt * 16 + l15) * 40 + kk + lhi);
            uint32_t bB[8][2];
            #pragma unroll
            for (int nh = 0; nh < 4; nh++) {
                uint32_t t0, t1, t2, t3;
                ldm_x4_t(t0, t1, t2, t3,
                         Bs + (kk + l15) * 136 + wn * 64 + nh * 16 + lhi);
                bB[2 * nh][0] = t0; bB[2 * nh][1] = t1;
                bB[2 * nh + 1][0] = t2; bB[2 * nh + 1][1] = t3;
            }
            #pragma unroll
            for (int mt = 0; mt < 4; mt++)
                #pragma unroll
                for (int nt = 0; nt < 8; nt++)
                    mma_bf16(acc[mt][nt], aA[mt], bB[nt]);
        }
    }

    // Epilogue
    #pragma unroll
    for (int mt = 0; mt < 4; mt++) {
        int row = bm * 128 + wm * 64 + mt * 16 + gid;
        #pragma unroll
        for (int nt = 0; nt < 8; nt++) {
            int col = bn * 128 + wn * 64 + nt * 8 + 2 * tig;
            float bb0 = bias[col], bb1 = bias[col + 1];
            size_t i0 = (size_t)row * N + col;
            size_t i1 = i0 + 8 * (size_t)N;
            float v0 = acc[mt][nt][0] + bb0, v1 = acc[mt][nt][1] + bb1;
            float v2 = acc[mt][nt][2] + bb0, v3 = acc[mt][nt][3] + bb1;
            if (OUT_BF16) {
                __nv_bfloat16* C = (__nv_bfloat16*)outp;
                *reinterpret_cast<__nv_bfloat162*>(C + i0) = __floats2bfloat162_rn(v0, v1);
                *reinterpret_cast<__nv_bfloat162*>(C + i1) = __floats2bfloat162_rn(v2, v3);
            } else {
                float* C = (float*)outp;
                if (ADD_RES) { v0 += res[i0]; v1 += res[i0 + 1]; v2 += res[i1]; v3 += res[i1 + 1]; }
                C[i0] = v0; C[i0 + 1] = v1; C[i1] = v2; C[i1 + 1] = v3;
            }
        }
    }
}

// ---------------------------------------------------------------------------
// Flash attention: 128-row Q tile, 4 warps x two m16 row-groups, no-max
// exp2 softmax with bf16x2 MUFU (ex2.approx.bf16x2), l computed on the
// tensor core via a constant ones-column in the V pad (col 64 = 1, 65..71 = 0;
// cp.async only writes cols 0..63, so the pad persists across stages).
// Frame-0 shortcut; 2-buffer cp.async KV (round-12 pipeline).
// ---------------------------------------------------------------------------
#define AT_QROWS   128
#define AT_SMEM    ((AT_QROWS * 72 + 2 * 64 * 72 + 2 * 64 * 72) * 2)  // 55296 B

__global__ __launch_bounds__(128)
void attn_kernel()
{
    extern __shared__ __align__(16) __nv_bfloat16 sm[];
    __nv_bfloat16* Qs = sm;                       // [128][72]
    __nv_bfloat16* Kb = sm + AT_QROWS * 72;       // [2][64][72]
    __nv_bfloat16* Vb = Kb + 2 * 64 * 72;         // [2][64][72]

    const int qt = blockIdx.x, h = blockIdx.y, bfi = blockIdx.z;
    const int bf0 = bfi & ~(N_FR - 1);
    const int nt_loop = ((bfi & (N_FR - 1)) == 0) ? 16 : 32;  // frame-0 shortcut
    const int tid = threadIdx.x;
    const int w = tid >> 5, lane = tid & 31;
    const int gid = lane >> 2, tig = lane & 3;
    const int l15 = lane & 15, lhi = (lane >> 4) << 3;

    // Stage Q tile, pre-scaled by 0.125 * log2(e)
    {
        const float qsc = 0.125f * 1.44269504f;
        #pragma unroll
        for (int i = 0; i < 8; i++) {
            int idx = tid + i * 128;
            int r = idx >> 3, c = (idx & 7) * 8;
            const __nv_bfloat16* p = g_q + (size_t)(bfi * SEQ + qt * AT_QROWS + r) * D_MODEL + h * HDIM + c;
            uint4 v = *reinterpret_cast<const uint4*>(p);
            __nv_bfloat16* pe = reinterpret_cast<__nv_bfloat16*>(&v);
            #pragma unroll
            for (int j = 0; j < 8; j++)
                pe[j] = __float2bfloat16_rn(__bfloat162float(pe[j]) * qsc);
            *reinterpret_cast<uint4*>(Qs + r * 72 + c) = v;
        }
    }

    auto stageKV = [&](int buf, int t) {
        const int sbf = (t < 16) ? bf0 : bfi;
        const int k0 = (t & 15) * 64;
        #pragma unroll
        for (int i = 0; i < 4; i++) {
            int idx = tid + i * 128;
            int r = idx >> 3, c = (idx & 7) * 8;
            size_t base = (size_t)(sbf * SEQ + k0 + r) * D_MODEL + h * HDIM + c;
            cp16(Kb + buf * 4608 + r * 72 + c, g_k + base);
            cp16(Vb + buf * 4608 + r * 72 + c, g_v + base);
        }
        cp_commit();
    };

    stageKV(0, 0);

    // Init V pad columns once (both buffers): col 64 = 1.0, cols 65..71 = 0.
    // cp.async only ever writes cols 0..63, so this persists across all stages.
    {
        int b = tid >> 6, r = tid & 63;       // 128 threads cover 2 x 64 rows
        __nv_bfloat16* row = Vb + b * 4608 + r * 72 + 64;
        row[0] = __float2bfloat16_rn(1.f);
        #pragma unroll
        for (int j = 1; j < 8; j++) row[j] = __float2bfloat16_rn(0.f);
    }
    __syncthreads();

    // Hoist Q fragments and the constant ones-column V fragment
    uint32_t qf[2][4][4];
    #pragma unroll
    for (int g = 0; g < 2; g++)
        #pragma unroll
        for (int kj = 0; kj < 4; kj++)
            ldm_x4(qf[g][kj][0], qf[g][kj][1], qf[g][kj][2], qf[g][kj][3],
                   Qs + (g * 64 + w * 16 + l15) * 72 + kj * 16 + lhi);

    uint32_t onesB[2];      // constant B fragment: 16(k) x 8(n), col 64 = ones
    ldm_x2_t(onesB[0], onesB[1], Vb + l15 * 72 + 64);

    float oacc[2][8][4];
    #pragma unroll
    for (int g = 0; g < 2; g++)
        #pragma unroll
        for (int nt = 0; nt < 8; nt++)
            #pragma unroll
            for (int i = 0; i < 4; i++) oacc[g][nt][i] = 0.f;
    float lacc[2][4];       // l accumulators (col 64 lives in tig==0, d[0]/d[2])
    #pragma unroll
    for (int g = 0; g < 2; g++)
        #pragma unroll
        for (int i = 0; i < 4; i++) lacc[g][i] = 0.f;

    int buf = 0;
    for (int t = 0; t < nt_loop; t++) {
        cp_wait0();
        __syncthreads();
        if (t + 1 < nt_loop) stageKV(buf ^ 1, t + 1);

        // S = Q @ K^T (log2 units)
        float sacc[2][8][4];
        #pragma unroll
        for (int g = 0; g < 2; g++)
            #pragma unroll
            for (int nt = 0; nt < 8; nt++)
                #pragma unroll
                for (int i = 0; i < 4; i++) sacc[g][nt][i] = 0.f;

        #pragma unroll
        for (int ntp = 0; ntp < 4; ntp++) {
            #pragma unroll
            for (int kj = 0; kj < 4; kj++) {
                uint32_t t0, t1, t2, t3;
                ldm_x4(t0, t1, t2, t3, Kb + buf * 4608 + (ntp * 16 + l15) * 72 + kj * 16 + lhi);
                uint32_t be[2] = {t0, t2};
                uint32_t bo[2] = {t1, t3};
                #pragma unroll
                for (int g = 0; g < 2; g++) {
                    mma_bf16(sacc[g][2 * ntp],     qf[g][kj], be);
                    mma_bf16(sacc[g][2 * ntp + 1], qf[g][kj], bo);
                }
            }
        }

        // p = exp2(s) directly in bf16x2 (these ARE the PV A-fragments)
        uint32_t pacc[2][8][2];
        #pragma unroll
        for (int g = 0; g < 2; g++)
            #pragma unroll
            for (int nt = 0; nt < 8; nt++) {
                pacc[g][nt][0] = ex2_bf16x2(cvt_bf16x2(sacc[g][nt][0], sacc[g][nt][1]));
                pacc[g][nt][1] = ex2_bf16x2(cvt_bf16x2(sacc[g][nt][2], sacc[g][nt][3]));
            }

        // O += P @ V ; l += P @ ones (extra n=8 MMA on the constant fragment)
        #pragma unroll
        for (int kj = 0; kj < 4; kj++) {
            uint32_t ap[2][4];
            #pragma unroll
            for (int g = 0; g < 2; g++) {
                ap[g][0] = pacc[g][2 * kj][0];
                ap[g][1] = pacc[g][2 * kj][1];
                ap[g][2] = pacc[g][2 * kj + 1][0];
                ap[g][3] = pacc[g][2 * kj + 1][1];
            }
            int vrow = kj * 16 + ((lane >> 3) & 1) * 8 + (lane & 7);
            #pragma unroll
            for (int dp = 0; dp < 4; dp++) {
                int vcol = dp * 16 + ((lane >> 4) & 1) * 8;
                uint32_t b0, b1, b2, b3;
                ldm_x4_t(b0, b1, b2, b3, Vb + buf * 4608 + vrow * 72 + vcol);
                uint32_t bb0[2] = {b0, b1};
                uint32_t bb1[2] = {b2, b3};
                #pragma unroll
                for (int g = 0; g < 2; g++) {
                    mma_bf16(oacc[g][2 * dp],     ap[g], bb0);
                    mma_bf16(oacc[g][2 * dp + 1], ap[g], bb1);
                }
            }
            #pragma unroll
            for (int g = 0; g < 2; g++)
                mma_bf16(lacc[g], ap[g], onesB);
        }
        buf ^= 1;
    }

    // l lives in the tig==0 lane of each row-quad (col 64): broadcast it.
    #pragma unroll
    for (int g = 0; g < 2; g++) {
        float l0 = __shfl_sync(0xffffffffu, lacc[g][0], lane & 28);
        float l1 = __shfl_sync(0xffffffffu, lacc[g][2], lane & 28);
        const int r0 = g * 64 + w * 16 + gid;
        const float inv0 = 1.f / l0, inv1 = 1.f / l1;
        #pragma unroll
        for (int nt = 0; nt < 8; nt++) {
            int dcol = h * HDIM + nt * 8 + 2 * tig;
            size_t b0 = (size_t)(bfi * SEQ + qt * AT_QROWS + r0) * D_MODEL + dcol;
            size_t b1 = b0 + 8 * (size_t)D_MODEL;
            *reinterpret_cast<__nv_bfloat162*>(g_attn + b0) =
                __floats2bfloat162_rn(oacc[g][nt][0] * inv0, oacc[g][nt][1] * inv0);
            *reinterpret_cast<__nv_bfloat162*>(g_attn + b1) =
                __floats2bfloat162_rn(oacc[g][nt][2] * inv1, oacc[g][nt][3] * inv1);
        }
    }
}

// ---------------------------------------------------------------------------

extern "C" void kernel_launch(void* const* d_in, const int* in_sizes, int n_in,
                              void* d_out, int out_size)
{
    const float* hs = (const float*)d_in[0];
    const float* Wq = (const float*)d_in[1];
    const float* Wk = (const float*)d_in[2];
    const float* Wv = (const float*)d_in[3];
    const float* Wo = (const float*)d_in[4];
    const float* bq = (const float*)d_in[5];
    const float* bk = (const float*)d_in[6];
    const float* bv = (const float*)d_in[7];
    const float* bo = (const float*)d_in[8];
    float* out = (float*)d_out;

    __nv_bfloat16 *hsb, *wqb, *wkb, *wvb, *wob, *qp, *kp, *vp, *ap;
    cudaGetSymbolAddress((void**)&hsb, g_hs);
    cudaGetSymbolAddress((void**)&wqb, g_wq);
    cudaGetSymbolAddress((void**)&wkb, g_wk);
    cudaGetSymbolAddress((void**)&wvb, g_wv);
    cudaGetSymbolAddress((void**)&wob, g_wo);
    cudaGetSymbolAddress((void**)&qp, g_q);
    cudaGetSymbolAddress((void**)&kp, g_k);
    cudaGetSymbolAddress((void**)&vp, g_v);
    cudaGetSymbolAddress((void**)&ap, g_attn);

    const int n_hs = M_TOT * D_MODEL, n_w = D_MODEL * D_MODEL;
    cvt_kernel<<<n_hs / 4 / 256, 256>>>(hs, hsb, n_hs);
    cvt4_kernel<<<dim3(n_w / 4 / 256, 1, 4), 256>>>(Wq, Wk, Wv, Wo, wqb, wkb, wvb, wob, n_w);

    cudaFuncSetAttribute((const void*)gemm_kernel<true, false>,
                         cudaFuncAttributeMaxDynamicSharedMemorySize, G_SMEM);
    cudaFuncSetAttribute((const void*)gemm_kernel<false, true>,
                         cudaFuncAttributeMaxDynamicSharedMemorySize, G_SMEM);
    cudaFuncSetAttribute((const void*)attn_kernel,
                         cudaFuncAttributeMaxDynamicSharedMemorySize, AT_SMEM);

    // Fused QKV: grid.x = 30 (3 weights x 10 n-tiles of 128)
    gemm_kernel<true, false><<<dim3(30, M_TOT / 128), 128, G_SMEM>>>(
        hsb, wqb, wkb, wvb, bq, bk, bv, qp, kp, vp, nullptr, M_TOT, D_MODEL, D_MODEL);

    attn_kernel<<<dim3(SEQ / AT_QROWS, N_HEADS, N_BF), 128, AT_SMEM>>>();

    gemm_kernel<false, true><<<dim3(10, M_TOT / 128), 128, G_SMEM>>>(
        ap, wob, wob, wob, bo, bo, bo, out, out, out, hs, M_TOT, D_MODEL, D_MODEL);
}

// round 16
// speedup vs baseline: 1.1092x; 1.0040x over previous
#include <cuda_runtime.h>
#include <cuda_bf16.h>
#include <cstdint>

#define D_MODEL 1280
#define SEQ     1024
#define N_BF    8
#define N_FR    4
#define N_HEADS 20
#define HDIM    64
#define M_TOT   (N_BF*SEQ)   // 8192

// Scratch (allocation-free rule: device globals). All bf16.
__device__ __nv_bfloat16 g_hs[(size_t)M_TOT * D_MODEL];
__device__ __nv_bfloat16 g_wq[(size_t)D_MODEL * D_MODEL];
__device__ __nv_bfloat16 g_wk[(size_t)D_MODEL * D_MODEL];
__device__ __nv_bfloat16 g_wv[(size_t)D_MODEL * D_MODEL];
__device__ __nv_bfloat16 g_wo[(size_t)D_MODEL * D_MODEL];
__device__ __nv_bfloat16 g_q[(size_t)M_TOT * D_MODEL];
__device__ __nv_bfloat16 g_k[(size_t)M_TOT * D_MODEL];
__device__ __nv_bfloat16 g_v[(size_t)M_TOT * D_MODEL];
__device__ __nv_bfloat16 g_attn[(size_t)M_TOT * D_MODEL];

__device__ __forceinline__ void mma_bf16(float d[4], const uint32_t a[4], const uint32_t b[2]) {
    asm volatile(
        "mma.sync.aligned.m16n8k16.row.col.f32.bf16.bf16.f32 "
        "{%0,%1,%2,%3}, {%4,%5,%6,%7}, {%8,%9}, {%0,%1,%2,%3};\n"
        : "+f"(d[0]), "+f"(d[1]), "+f"(d[2]), "+f"(d[3])
        : "r"(a[0]), "r"(a[1]), "r"(a[2]), "r"(a[3]),
          "r"(b[0]), "r"(b[1]));
}

__device__ __forceinline__ void ldm_x4(uint32_t& r0, uint32_t& r1, uint32_t& r2, uint32_t& r3,
                                       const void* p) {
    uint32_t a = (uint32_t)__cvta_generic_to_shared(p);
    asm volatile("ldmatrix.sync.aligned.m8n8.x4.shared.b16 {%0,%1,%2,%3}, [%4];\n"
                 : "=r"(r0), "=r"(r1), "=r"(r2), "=r"(r3) : "r"(a));
}

__device__ __forceinline__ void ldm_x4_t(uint32_t& r0, uint32_t& r1, uint32_t& r2, uint32_t& r3,
                                         const void* p) {
    uint32_t a = (uint32_t)__cvta_generic_to_shared(p);
    asm volatile("ldmatrix.sync.aligned.m8n8.x4.trans.shared.b16 {%0,%1,%2,%3}, [%4];\n"
                 : "=r"(r0), "=r"(r1), "=r"(r2), "=r"(r3) : "r"(a));
}

__device__ __forceinline__ void ldm_x2_t(uint32_t& r0, uint32_t& r1, const void* p) {
    uint32_t a = (uint32_t)__cvta_generic_to_shared(p);
    asm volatile("ldmatrix.sync.aligned.m8n8.x2.trans.shared.b16 {%0,%1}, [%2];\n"
                 : "=r"(r0), "=r"(r1) : "r"(a));
}

// pack (lo,hi) fp32 -> bf16x2 (matches __floats2bfloat162_rn(lo,hi) layout)
__device__ __forceinline__ uint32_t cvt_bf16x2(float lo, float hi) {
    uint32_t d;
    asm("cvt.rn.bf16x2.f32 %0, %1, %2;" : "=r"(d) : "f"(hi), "f"(lo));
    return d;
}

__device__ __forceinline__ uint32_t ex2_bf16x2(uint32_t a) {
    uint32_t d;
    asm("ex2.approx.ftz.bf16x2 %0, %1;" : "=r"(d) : "r"(a));
    return d;
}

__device__ __forceinline__ void cp16(void* smem, const void* gmem) {
    uint32_t s = (uint32_t)__cvta_generic_to_shared(smem);
    asm volatile("cp.async.cg.shared.global [%0], [%1], 16;\n" :: "r"(s), "l"(gmem));
}
__device__ __forceinline__ void cp_commit() { asm volatile("cp.async.commit_group;\n"); }
__device__ __forceinline__ void cp_wait0()  { asm volatile("cp.async.wait_group 0;\n"); }
__device__ __forceinline__ void cp_wait2()  { asm volatile("cp.async.wait_group 2;\n"); }

// ---------------------------------------------------------------------------
// fp32 -> bf16 converters (round-12 exact)
// ---------------------------------------------------------------------------
__global__ void cvt_kernel(const float* __restrict__ in, __nv_bfloat16* __restrict__ out, int n)
{
    int i = (blockIdx.x * blockDim.x + threadIdx.x) * 4;
    if (i >= n) return;
    float4 v = *reinterpret_cast<const float4*>(in + i);
    __nv_bfloat162 lo = __floats2bfloat162_rn(v.x, v.y);
    __nv_bfloat162 hi = __floats2bfloat162_rn(v.z, v.w);
    uint2 o = make_uint2(*reinterpret_cast<uint32_t*>(&lo), *reinterpret_cast<uint32_t*>(&hi));
    *reinterpret_cast<uint2*>(out + i) = o;
}

__global__ void cvt4_kernel(const float* __restrict__ s0, const float* __restrict__ s1,
                            const float* __restrict__ s2, const float* __restrict__ s3,
                            __nv_bfloat16* __restrict__ d0, __nv_bfloat16* __restrict__ d1,
                            __nv_bfloat16* __restrict__ d2, __nv_bfloat16* __restrict__ d3,
                            int n)
{
    const float* in = (blockIdx.z == 0) ? s0 : (blockIdx.z == 1) ? s1
                    : (blockIdx.z == 2) ? s2 : s3;
    __nv_bfloat16* out = (blockIdx.z == 0) ? d0 : (blockIdx.z == 1) ? d1
                       : (blockIdx.z == 2) ? d2 : d3;
    int i = (blockIdx.x * blockDim.x + threadIdx.x) * 4;
    if (i >= n) return;
    float4 v = *reinterpret_cast<const float4*>(in + i);
    __nv_bfloat162 lo = __floats2bfloat162_rn(v.x, v.y);
    __nv_bfloat162 hi = __floats2bfloat162_rn(v.z, v.w);
    uint2 o = make_uint2(*reinterpret_cast<uint32_t*>(&lo), *reinterpret_cast<uint32_t*>(&hi));
    *reinterpret_cast<uint2*>(out + i) = o;
}

// ---------------------------------------------------------------------------
// GEMM (round-12 exact): 128x128 block, 4 warps of 64x64, 32-deep k-stages,
// 4-stage cp.async pipeline (wait_group 2), 2 CTAs/SM.
// ---------------------------------------------------------------------------
#define GK_NSTG   (D_MODEL / 32)   // 40
#define GA_ELEMS  (128 * 40)
#define GB_ELEMS  (32 * 136)
#define G_SMEM    ((4 * GA_ELEMS + 4 * GB_ELEMS) * 2)   // 75776 B

template<bool OUT_BF16, bool ADD_RES>
__global__ __launch_bounds__(128, 2)
void gemm_kernel(const __nv_bfloat16* __restrict__ A,
                 const __nv_bfloat16* __restrict__ W0, const __nv_bfloat16* __restrict__ W1,
                 const __nv_bfloat16* __restrict__ W2,
                 const float* __restrict__ b0, const float* __restrict__ b1,
                 const float* __restrict__ b2,
                 void* __restrict__ o0, void* __restrict__ o1, void* __restrict__ o2,
                 const float* __restrict__ res, int M, int N, int K)
{
    extern __shared__ __align__(16) char smem[];
    __nv_bfloat16* Abase = reinterpret_cast<__nv_bfloat16*>(smem);
    __nv_bfloat16* Bbase = Abase + 4 * GA_ELEMS;

    const int bm = blockIdx.y;
    const int which = blockIdx.x / 10, bn = blockIdx.x % 10;
    const __nv_bfloat16* W = (which == 0) ? W0 : (which == 1) ? W1 : W2;
    const float* bias = (which == 0) ? b0 : (which == 1) ? b1 : b2;
    void* outp = (which == 0) ? o0 : (which == 1) ? o1 : o2;

    const int tid = threadIdx.x;
    const int warp = tid >> 5, lane = tid & 31;
    const int wm = warp >> 1, wn = warp & 1;     // 2x2 warp grid, each 64x64
    const int gid = lane >> 2, tig = lane & 3;
    const int l15 = lane & 15, lhi = (lane >> 4) << 3;

    float acc[4][8][4];
    #pragma unroll
    for (int mt = 0; mt < 4; mt++)
        #pragma unroll
        for (int nt = 0; nt < 8; nt++)
            #pragma unroll
            for (int i = 0; i < 4; i++) acc[mt][nt][i] = 0.f;

    auto stage = [&](int s) {
        const int buf = s & 3;
        const int kt = s * 32;
        __nv_bfloat16* As = Abase + buf * GA_ELEMS;
        __nv_bfloat16* Bs = Bbase + buf * GB_ELEMS;
        #pragma unroll
        for (int i = 0; i < 4; i++) {
            int idx = tid + i * 128;
            int r = idx >> 2, c = (idx & 3) * 8;
            cp16(As + r * 40 + c, A + (size_t)(bm * 128 + r) * K + kt + c);
        }
        #pragma unroll
        for (int i = 0; i < 4; i++) {
            int idx = tid + i * 128;
            int r = idx >> 4, c = (idx & 15) * 8;
            cp16(Bs + r * 136 + c, W + (size_t)(kt + r) * N + bn * 128 + c);
        }
        cp_commit();
    };

    stage(0); stage(1); stage(2);

    for (int s = 0; s < GK_NSTG; s++) {
        cp_wait2();
        __syncthreads();
        if (s + 3 < GK_NSTG) stage(s + 3);
        else cp_commit();

        const int buf = s & 3;
        const __nv_bfloat16* As = Abase + buf * GA_ELEMS;
        const __nv_bfloat16* Bs = Bbase + buf * GB_ELEMS;

        #pragma unroll
        for (int kk = 0; kk < 32; kk += 16) {
            uint32_t aA[4][4];
            #pragma unroll
            for (int mt = 0; mt < 4; mt++)
                ldm_x4(aA[mt][0], aA[mt][1], aA[mt][2], aA[mt][3],
                       As + (wm * 64 + mt * 16 + l15) * 40 + kk + lhi);
            uint32_t bB[8][2];
            #pragma unroll
            for (int nh = 0; nh < 4; nh++) {
                uint32_t t0, t1, t2, t3;
                ldm_x4_t(t0, t1, t2, t3,
                         Bs + (kk + l15) * 136 + wn * 64 + nh * 16 + lhi);
                bB[2 * nh][0] = t0; bB[2 * nh][1] = t1;
                bB[2 * nh + 1][0] = t2; bB[2 * nh + 1][1] = t3;
            }
            #pragma unroll
            for (int mt = 0; mt < 4; mt++)
                #pragma unroll
                for (int nt = 0; nt < 8; nt++)
                    mma_bf16(acc[mt][nt], aA[mt], bB[nt]);
        }
    }

    // Epilogue
    #pragma unroll
    for (int mt = 0; mt < 4; mt++) {
        int row = bm * 128 + wm * 64 + mt * 16 + gid;
        #pragma unroll
        for (int nt = 0; nt < 8; nt++) {
            int col = bn * 128 + wn * 64 + nt * 8 + 2 * tig;
            float bb0 = bias[col], bb1 = bias[col + 1];
            size_t i0 = (size_t)row * N + col;
            size_t i1 = i0 + 8 * (size_t)N;
            float v0 = acc[mt][nt][0] + bb0, v1 = acc[mt][nt][1] + bb1;
            float v2 = acc[mt][nt][2] + bb0, v3 = acc[mt][nt][3] + bb1;
            if (OUT_BF16) {
                __nv_bfloat16* C = (__nv_bfloat16*)outp;
                *reinterpret_cast<__nv_bfloat162*>(C + i0) = __floats2bfloat162_rn(v0, v1);
                *reinterpret_cast<__nv_bfloat162*>(C + i1) = __floats2bfloat162_rn(v2, v3);
            } else {
                float* C = (float*)outp;
                if (ADD_RES) { v0 += res[i0]; v1 += res[i0 + 1]; v2 += res[i1]; v3 += res[i1 + 1]; }
                C[i0] = v0; C[i0 + 1] = v1; C[i1] = v2; C[i1 + 1] = v3;
            }
        }
    }
}

// ---------------------------------------------------------------------------
// Flash attention: 128-row Q tile, 4 warps x two m16 row-groups, no-max
// exp2 softmax with bf16x2 MUFU (ex2.approx.bf16x2), l computed on the
// tensor core via a constant ones-column in the V pad (col 64 = 1, 65..71 = 0;
// cp.async only writes cols 0..63, so the pad persists across stages).
// Frame-0 shortcut; 2-buffer cp.async KV (round-12 pipeline).
// ---------------------------------------------------------------------------
#define AT_QROWS   128
#define AT_SMEM    ((AT_QROWS * 72 + 2 * 64 * 72 + 2 * 64 * 72) * 2)  // 55296 B

__global__ __launch_bounds__(128)
void attn_kernel()
{
    extern __shared__ __align__(16) __nv_bfloat16 sm[];
    __nv_bfloat16* Qs = sm;                       // [128][72]
    __nv_bfloat16* Kb = sm + AT_QROWS * 72;       // [2][64][72]
    __nv_bfloat16* Vb = Kb + 2 * 64 * 72;         // [2][64][72]

    const int qt = blockIdx.x, h = blockIdx.y, bfi = blockIdx.z;
    const int bf0 = bfi & ~(N_FR - 1);
    const int nt_loop = ((bfi & (N_FR - 1)) == 0) ? 16 : 32;  // frame-0 shortcut
    const int tid = threadIdx.x;
    const int w = tid >> 5, lane = tid & 31;
    const int gid = lane >> 2, tig = lane & 3;
    const int l15 = lane & 15, lhi = (lane >> 4) << 3;

    // Stage Q tile, pre-scaled by 0.125 * log2(e)
    {
        const float qsc = 0.125f * 1.44269504f;
        #pragma unroll
        for (int i = 0; i < 8; i++) {
            int idx = tid + i * 128;
            int r = idx >> 3, c = (idx & 7) * 8;
            const __nv_bfloat16* p = g_q + (size_t)(bfi * SEQ + qt * AT_QROWS + r) * D_MODEL + h * HDIM + c;
            uint4 v = *reinterpret_cast<const uint4*>(p);
            __nv_bfloat16* pe = reinterpret_cast<__nv_bfloat16*>(&v);
            #pragma unroll
            for (int j = 0; j < 8; j++)
                pe[j] = __float2bfloat16_rn(__bfloat162float(pe[j]) * qsc);
            *reinterpret_cast<uint4*>(Qs + r * 72 + c) = v;
        }
    }

    auto stageKV = [&](int buf, int t) {
        const int sbf = (t < 16) ? bf0 : bfi;
        const int k0 = (t & 15) * 64;
        #pragma unroll
        for (int i = 0; i < 4; i++) {
            int idx = tid + i * 128;
            int r = idx >> 3, c = (idx & 7) * 8;
            size_t base = (size_t)(sbf * SEQ + k0 + r) * D_MODEL + h * HDIM + c;
            cp16(Kb + buf * 4608 + r * 72 + c, g_k + base);
            cp16(Vb + buf * 4608 + r * 72 + c, g_v + base);
        }
        cp_commit();
    };

    stageKV(0, 0);

    // Init V pad columns once (both buffers): col 64 = 1.0, cols 65..71 = 0.
    // cp.async only ever writes cols 0..63, so this persists across all stages.
    {
        int b = tid >> 6, r = tid & 63;       // 128 threads cover 2 x 64 rows
        __nv_bfloat16* row = Vb + b * 4608 + r * 72 + 64;
        row[0] = __float2bfloat16_rn(1.f);
        #pragma unroll
        for (int j = 1; j < 8; j++) row[j] = __float2bfloat16_rn(0.f);
    }
    __syncthreads();

    // Hoist Q fragments and the constant ones-column V fragment
    uint32_t qf[2][4][4];
    #pragma unroll
    for (int g = 0; g < 2; g++)
        #pragma unroll
        for (int kj = 0; kj < 4; kj++)
            ldm_x4(qf[g][kj][0], qf[g][kj][1], qf[g][kj][2], qf[g][kj][3],
                   Qs + (g * 64 + w * 16 + l15) * 72 + kj * 16 + lhi);

    uint32_t onesB[2];      // constant B fragment: 16(k) x 8(n), col 64 = ones
    ldm_x2_t(onesB[0], onesB[1], Vb + l15 * 72 + 64);

    float oacc[2][8][4];
    #pragma unroll
    for (int g = 0; g < 2; g++)
        #pragma unroll
        for (int nt = 0; nt < 8; nt++)
            #pragma unroll
            for (int i = 0; i < 4; i++) oacc[g][nt][i] = 0.f;
    float lacc[2][4];       // l accumulators (col 64 lives in tig==0, d[0]/d[2])
    #pragma unroll
    for (int g = 0; g < 2; g++)
        #pragma unroll
        for (int i = 0; i < 4; i++) lacc[g][i] = 0.f;

    int buf = 0;
    for (int t = 0; t < nt_loop; t++) {
        cp_wait0();
        __syncthreads();
        if (t + 1 < nt_loop) stageKV(buf ^ 1, t + 1);

        // S = Q @ K^T (log2 units)
        float sacc[2][8][4];
        #pragma unroll
        for (int g = 0; g < 2; g++)
            #pragma unroll
            for (int nt = 0; nt < 8; nt++)
                #pragma unroll
                for (int i = 0; i < 4; i++) sacc[g][nt][i] = 0.f;

        #pragma unroll
        for (int ntp = 0; ntp < 4; ntp++) {
            #pragma unroll
            for (int kj = 0; kj < 4; kj++) {
                uint32_t t0, t1, t2, t3;
                ldm_x4(t0, t1, t2, t3, Kb + buf * 4608 + (ntp * 16 + l15) * 72 + kj * 16 + lhi);
                uint32_t be[2] = {t0, t2};
                uint32_t bo[2] = {t1, t3};
                #pragma unroll
                for (int g = 0; g < 2; g++) {
                    mma_bf16(sacc[g][2 * ntp],     qf[g][kj], be);
                    mma_bf16(sacc[g][2 * ntp + 1], qf[g][kj], bo);
                }
            }
        }

        // p = exp2(s) directly in bf16x2 (these ARE the PV A-fragments)
        uint32_t pacc[2][8][2];
        #pragma unroll
        for (int g = 0; g < 2; g++)
            #pragma unroll
            for (int nt = 0; nt < 8; nt++) {
                pacc[g][nt][0] = ex2_bf16x2(cvt_bf16x2(sacc[g][nt][0], sacc[g][nt][1]));
                pacc[g][nt][1] = ex2_bf16x2(cvt_bf16x2(sacc[g][nt][2], sacc[g][nt][3]));
            }

        // O += P @ V ; l += P @ ones (extra n=8 MMA on the constant fragment)
        #pragma unroll
        for (int kj = 0; kj < 4; kj++) {
            uint32_t ap[2][4];
            #pragma unroll
            for (int g = 0; g < 2; g++) {
                ap[g][0] = pacc[g][2 * kj][0];
                ap[g][1] = pacc[g][2 * kj][1];
                ap[g][2] = pacc[g][2 * kj + 1][0];
                ap[g][3] = pacc[g][2 * kj + 1][1];
            }
            int vrow = kj * 16 + ((lane >> 3) & 1) * 8 + (lane & 7);
            #pragma unroll
            for (int dp = 0; dp < 4; dp++) {
                int vcol = dp * 16 + ((lane >> 4) & 1) * 8;
                uint32_t b0, b1, b2, b3;
                ldm_x4_t(b0, b1, b2, b3, Vb + buf * 4608 + vrow * 72 + vcol);
                uint32_t bb0[2] = {b0, b1};
                uint32_t bb1[2] = {b2, b3};
                #pragma unroll
                for (int g = 0; g < 2; g++) {
                    mma_bf16(oacc[g][2 * dp],     ap[g], bb0);
                    mma_bf16(oacc[g][2 * dp + 1], ap[g], bb1);
                }
            }
            #pragma unroll
            for (int g = 0; g < 2; g++)
                mma_bf16(lacc[g], ap[g], onesB);
        }
        buf ^= 1;
    }

    // l lives in the tig==0 lane of each row-quad (col 64): broadcast it.
    #pragma unroll
    for (int g = 0; g < 2; g++) {
        float l0 = __shfl_sync(0xffffffffu, lacc[g][0], lane & 28);
        float l1 = __shfl_sync(0xffffffffu, lacc[g][2], lane & 28);
        const int r0 = g * 64 + w * 16 + gid;
        const float inv0 = 1.f / l0, inv1 = 1.f / l1;
        #pragma unroll
        for (int nt = 0; nt < 8; nt++) {
            int dcol = h * HDIM + nt * 8 + 2 * tig;
            size_t b0 = (size_t)(bfi * SEQ + qt * AT_QROWS + r0) * D_MODEL + dcol;
            size_t b1 = b0 + 8 * (size_t)D_MODEL;
            *reinterpret_cast<__nv_bfloat162*>(g_attn + b0) =
                __floats2bfloat162_rn(oacc[g][nt][0] * inv0, oacc[g][nt][1] * inv0);
            *reinterpret_cast<__nv_bfloat162*>(g_attn + b1) =
                __floats2bfloat162_rn(oacc[g][nt][2] * inv1, oacc[g][nt][3] * inv1);
        }
    }
}

// ---------------------------------------------------------------------------

extern "C" void kernel_launch(void* const* d_in, const int* in_sizes, int n_in,
                              void* d_out, int out_size)
{
    const float* hs = (const float*)d_in[0];
    const float* Wq = (const float*)d_in[1];
    const float* Wk = (const float*)d_in[2];
    const float* Wv = (const float*)d_in[3];
    const float* Wo = (const float*)d_in[4];
    const float* bq = (const float*)d_in[5];
    const float* bk = (const float*)d_in[6];
    const float* bv = (const float*)d_in[7];
    const float* bo = (const float*)d_in[8];
    float* out = (float*)d_out;

    __nv_bfloat16 *hsb, *wqb, *wkb, *wvb, *wob, *qp, *kp, *vp, *ap;
    cudaGetSymbolAddress((void**)&hsb, g_hs);
    cudaGetSymbolAddress((void**)&wqb, g_wq);
    cudaGetSymbolAddress((void**)&wkb, g_wk);
    cudaGetSymbolAddress((void**)&wvb, g_wv);
    cudaGetSymbolAddress((void**)&wob, g_wo);
    cudaGetSymbolAddress((void**)&qp, g_q);
    cudaGetSymbolAddress((void**)&kp, g_k);
    cudaGetSymbolAddress((void**)&vp, g_v);
    cudaGetSymbolAddress((void**)&ap, g_attn);

    const int n_hs = M_TOT * D_MODEL, n_w = D_MODEL * D_MODEL;
    cvt_kernel<<<n_hs / 4 / 256, 256>>>(hs, hsb, n_hs);
    cvt4_kernel<<<dim3(n_w / 4 / 256, 1, 4), 256>>>(Wq, Wk, Wv, Wo, wqb, wkb, wvb, wob, n_w);

    cudaFuncSetAttribute((const void*)gemm_kernel<true, false>,
                         cudaFuncAttributeMaxDynamicSharedMemorySize, G_SMEM);
    cudaFuncSetAttribute((const void*)gemm_kernel<false, true>,
                         cudaFuncAttributeMaxDynamicSharedMemorySize, G_SMEM);
    cudaFuncSetAttribute((const void*)attn_kernel,
                         cudaFuncAttributeMaxDynamicSharedMemorySize, AT_SMEM);

    // Fused QKV: grid.x = 30 (3 weights x 10 n-tiles of 128)
    gemm_kernel<true, false><<<dim3(30, M_TOT / 128), 128, G_SMEM>>>(
        hsb, wqb, wkb, wvb, bq, bk, bv, qp, kp, vp, nullptr, M_TOT, D_MODEL, D_MODEL);

    attn_kernel<<<dim3(SEQ / AT_QROWS, N_HEADS, N_BF), 128, AT_SMEM>>>();

    gemm_kernel<false, true><<<dim3(10, M_TOT / 128), 128, G_SMEM>>>(
        ap, wob, wob, wob, bo, bo, bo, out, out, out, hs, M_TOT, D_MODEL, D_MODEL);
}

// round 17
// speedup vs baseline: 1.1798x; 1.0637x over previous
#include <cuda_runtime.h>
#include <cuda_bf16.h>
#include <cstdint>

#define D_MODEL 1280
#define SEQ     1024
#define N_BF    8
#define N_FR    4
#define N_HEADS 20
#define HDIM    64
#define M_TOT   (N_BF*SEQ)   // 8192

// Scratch (allocation-free rule: device globals). All bf16.
__device__ __nv_bfloat16 g_hs[(size_t)M_TOT * D_MODEL];
__device__ __nv_bfloat16 g_wq[(size_t)D_MODEL * D_MODEL];
__device__ __nv_bfloat16 g_wk[(size_t)D_MODEL * D_MODEL];
__device__ __nv_bfloat16 g_wv[(size_t)D_MODEL * D_MODEL];
__device__ __nv_bfloat16 g_wo[(size_t)D_MODEL * D_MODEL];
__device__ __nv_bfloat16 g_q[(size_t)M_TOT * D_MODEL];
__device__ __nv_bfloat16 g_k[(size_t)M_TOT * D_MODEL];
__device__ __nv_bfloat16 g_v[(size_t)M_TOT * D_MODEL];
__device__ __nv_bfloat16 g_attn[(size_t)M_TOT * D_MODEL];

__device__ __forceinline__ void mma_bf16(float d[4], const uint32_t a[4], const uint32_t b[2]) {
    asm volatile(
        "mma.sync.aligned.m16n8k16.row.col.f32.bf16.bf16.f32 "
        "{%0,%1,%2,%3}, {%4,%5,%6,%7}, {%8,%9}, {%0,%1,%2,%3};\n"
        : "+f"(d[0]), "+f"(d[1]), "+f"(d[2]), "+f"(d[3])
        : "r"(a[0]), "r"(a[1]), "r"(a[2]), "r"(a[3]),
          "r"(b[0]), "r"(b[1]));
}

__device__ __forceinline__ void ldm_x4(uint32_t& r0, uint32_t& r1, uint32_t& r2, uint32_t& r3,
                                       const void* p) {
    uint32_t a = (uint32_t)__cvta_generic_to_shared(p);
    asm volatile("ldmatrix.sync.aligned.m8n8.x4.shared.b16 {%0,%1,%2,%3}, [%4];\n"
                 : "=r"(r0), "=r"(r1), "=r"(r2), "=r"(r3) : "r"(a));
}

__device__ __forceinline__ void ldm_x4_t(uint32_t& r0, uint32_t& r1, uint32_t& r2, uint32_t& r3,
                                         const void* p) {
    uint32_t a = (uint32_t)__cvta_generic_to_shared(p);
    asm volatile("ldmatrix.sync.aligned.m8n8.x4.trans.shared.b16 {%0,%1,%2,%3}, [%4];\n"
                 : "=r"(r0), "=r"(r1), "=r"(r2), "=r"(r3) : "r"(a));
}

__device__ __forceinline__ void ldm_x2_t(uint32_t& r0, uint32_t& r1, const void* p) {
    uint32_t a = (uint32_t)__cvta_generic_to_shared(p);
    asm volatile("ldmatrix.sync.aligned.m8n8.x2.trans.shared.b16 {%0,%1}, [%2];\n"
                 : "=r"(r0), "=r"(r1) : "r"(a));
}

// pack (lo,hi) fp32 -> bf16x2 (matches __floats2bfloat162_rn(lo,hi) layout)
__device__ __forceinline__ uint32_t cvt_bf16x2(float lo, float hi) {
    uint32_t d;
    asm("cvt.rn.bf16x2.f32 %0, %1, %2;" : "=r"(d) : "f"(hi), "f"(lo));
    return d;
}

__device__ __forceinline__ uint32_t ex2_bf16x2(uint32_t a) {
    uint32_t d;
    asm("ex2.approx.ftz.bf16x2 %0, %1;" : "=r"(d) : "r"(a));
    return d;
}

__device__ __forceinline__ void cp16(void* smem, const void* gmem) {
    uint32_t s = (uint32_t)__cvta_generic_to_shared(smem);
    asm volatile("cp.async.cg.shared.global [%0], [%1], 16;\n" :: "r"(s), "l"(gmem));
}
__device__ __forceinline__ void cp_commit() { asm volatile("cp.async.commit_group;\n"); }
__device__ __forceinline__ void cp_wait0()  { asm volatile("cp.async.wait_group 0;\n"); }
__device__ __forceinline__ void cp_wait2()  { asm volatile("cp.async.wait_group 2;\n"); }

// ---------------------------------------------------------------------------
// fp32 -> bf16 converters (round-12 exact)
// ---------------------------------------------------------------------------
__global__ void cvt_kernel(const float* __restrict__ in, __nv_bfloat16* __restrict__ out, int n)
{
    int i = (blockIdx.x * blockDim.x + threadIdx.x) * 4;
    if (i >= n) return;
    float4 v = *reinterpret_cast<const float4*>(in + i);
    __nv_bfloat162 lo = __floats2bfloat162_rn(v.x, v.y);
    __nv_bfloat162 hi = __floats2bfloat162_rn(v.z, v.w);
    uint2 o = make_uint2(*reinterpret_cast<uint32_t*>(&lo), *reinterpret_cast<uint32_t*>(&hi));
    *reinterpret_cast<uint2*>(out + i) = o;
}

__global__ void cvt4_kernel(const float* __restrict__ s0, const float* __restrict__ s1,
                            const float* __restrict__ s2, const float* __restrict__ s3,
                            __nv_bfloat16* __restrict__ d0, __nv_bfloat16* __restrict__ d1,
                            __nv_bfloat16* __restrict__ d2, __nv_bfloat16* __restrict__ d3,
                            int n)
{
    const float* in = (blockIdx.z == 0) ? s0 : (blockIdx.z == 1) ? s1
                    : (blockIdx.z == 2) ? s2 : s3;
    __nv_bfloat16* out = (blockIdx.z == 0) ? d0 : (blockIdx.z == 1) ? d1
                       : (blockIdx.z == 2) ? d2 : d3;
    int i = (blockIdx.x * blockDim.x + threadIdx.x) * 4;
    if (i >= n) return;
    float4 v = *reinterpret_cast<const float4*>(in + i);
    __nv_bfloat162 lo = __floats2bfloat162_rn(v.x, v.y);
    __nv_bfloat162 hi = __floats2bfloat162_rn(v.z, v.w);
    uint2 o = make_uint2(*reinterpret_cast<uint32_t*>(&lo), *reinterpret_cast<uint32_t*>(&hi));
    *reinterpret_cast<uint2*>(out + i) = o;
}

// ---------------------------------------------------------------------------
// QKV GEMM (round-12/16 exact): 128x128 block, 4 warps of 64x64, 32-deep
// k-stages, 4-stage cp.async (wait_group 2), 2 CTAs/SM. bf16 out.
// ---------------------------------------------------------------------------
#define GK_NSTG   (D_MODEL / 32)   // 40
#define GA_ELEMS  (128 * 40)
#define GB_ELEMS  (32 * 136)
#define G_SMEM    ((4 * GA_ELEMS + 4 * GB_ELEMS) * 2)   // 75776 B

__global__ __launch_bounds__(128, 2)
void gemm_qkv_kernel(const __nv_bfloat16* __restrict__ A,
                     const __nv_bfloat16* __restrict__ W0, const __nv_bfloat16* __restrict__ W1,
                     const __nv_bfloat16* __restrict__ W2,
                     const float* __restrict__ b0, const float* __restrict__ b1,
                     const float* __restrict__ b2,
                     __nv_bfloat16* __restrict__ o0, __nv_bfloat16* __restrict__ o1,
                     __nv_bfloat16* __restrict__ o2)
{
    extern __shared__ __align__(16) char smem[];
    __nv_bfloat16* Abase = reinterpret_cast<__nv_bfloat16*>(smem);
    __nv_bfloat16* Bbase = Abase + 4 * GA_ELEMS;

    const int N = D_MODEL, K = D_MODEL;
    const int bm = blockIdx.y;
    const int which = blockIdx.x / 10, bn = blockIdx.x % 10;
    const __nv_bfloat16* W = (which == 0) ? W0 : (which == 1) ? W1 : W2;
    const float* bias = (which == 0) ? b0 : (which == 1) ? b1 : b2;
    __nv_bfloat16* outp = (which == 0) ? o0 : (which == 1) ? o1 : o2;

    const int tid = threadIdx.x;
    const int warp = tid >> 5, lane = tid & 31;
    const int wm = warp >> 1, wn = warp & 1;     // 2x2 warp grid, each 64x64
    const int gid = lane >> 2, tig = lane & 3;
    const int l15 = lane & 15, lhi = (lane >> 4) << 3;

    float acc[4][8][4];
    #pragma unroll
    for (int mt = 0; mt < 4; mt++)
        #pragma unroll
        for (int nt = 0; nt < 8; nt++)
            #pragma unroll
            for (int i = 0; i < 4; i++) acc[mt][nt][i] = 0.f;

    auto stage = [&](int s) {
        const int buf = s & 3;
        const int kt = s * 32;
        __nv_bfloat16* As = Abase + buf * GA_ELEMS;
        __nv_bfloat16* Bs = Bbase + buf * GB_ELEMS;
        #pragma unroll
        for (int i = 0; i < 4; i++) {
            int idx = tid + i * 128;
            int r = idx >> 2, c = (idx & 3) * 8;
            cp16(As + r * 40 + c, A + (size_t)(bm * 128 + r) * K + kt + c);
        }
        #pragma unroll
        for (int i = 0; i < 4; i++) {
            int idx = tid + i * 128;
            int r = idx >> 4, c = (idx & 15) * 8;
            cp16(Bs + r * 136 + c, W + (size_t)(kt + r) * N + bn * 128 + c);
        }
        cp_commit();
    };

    stage(0); stage(1); stage(2);

    for (int s = 0; s < GK_NSTG; s++) {
        cp_wait2();
        __syncthreads();
        if (s + 3 < GK_NSTG) stage(s + 3);
        else cp_commit();

        const int buf = s & 3;
        const __nv_bfloat16* As = Abase + buf * GA_ELEMS;
        const __nv_bfloat16* Bs = Bbase + buf * GB_ELEMS;

        #pragma unroll
        for (int kk = 0; kk < 32; kk += 16) {
            uint32_t aA[4][4];
            #pragma unroll
            for (int mt = 0; mt < 4; mt++)
                ldm_x4(aA[mt][0], aA[mt][1], aA[mt][2], aA[mt][3],
                       As + (wm * 64 + mt * 16 + l15) * 40 + kk + lhi);
            uint32_t bB[8][2];
            #pragma unroll
            for (int nh = 0; nh < 4; nh++) {
                uint32_t t0, t1, t2, t3;
                ldm_x4_t(t0, t1, t2, t3,
                         Bs + (kk + l15) * 136 + wn * 64 + nh * 16 + lhi);
                bB[2 * nh][0] = t0; bB[2 * nh][1] = t1;
                bB[2 * nh + 1][0] = t2; bB[2 * nh + 1][1] = t3;
            }
            #pragma unroll
            for (int mt = 0; mt < 4; mt++)
                #pragma unroll
                for (int nt = 0; nt < 8; nt++)
                    mma_bf16(acc[mt][nt], aA[mt], bB[nt]);
        }
    }

    #pragma unroll
    for (int mt = 0; mt < 4; mt++) {
        int row = bm * 128 + wm * 64 + mt * 16 + gid;
        #pragma unroll
        for (int nt = 0; nt < 8; nt++) {
            int col = bn * 128 + wn * 64 + nt * 8 + 2 * tig;
            float bb0 = bias[col], bb1 = bias[col + 1];
            size_t i0 = (size_t)row * N + col;
            size_t i1 = i0 + 8 * (size_t)N;
            *reinterpret_cast<__nv_bfloat162*>(outp + i0) =
                __floats2bfloat162_rn(acc[mt][nt][0] + bb0, acc[mt][nt][1] + bb1);
            *reinterpret_cast<__nv_bfloat162*>(outp + i1) =
                __floats2bfloat162_rn(acc[mt][nt][2] + bb0, acc[mt][nt][3] + bb1);
        }
    }
}

// ---------------------------------------------------------------------------
// Wo GEMM, M64 variant: block 64x128, 128 thr, 2x2 warps of 32x64 (acc 64
// regs). Grid 10x128 = 1280 CTAs -> 2.9 waves over 444 slots (3 CTAs/SM):
// kills the 2.16-wave quantization tail the profiler showed at M128.
// fp32 out + bias + residual.
// ---------------------------------------------------------------------------
#define G64A_ELEMS  (64 * 40)
#define G64B_ELEMS  (32 * 136)
#define G64_SMEM    ((4 * G64A_ELEMS + 4 * G64B_ELEMS) * 2)   // 55296 B

__global__ __launch_bounds__(128, 3)
void gemm_wo_kernel(const __nv_bfloat16* __restrict__ A,
                    const __nv_bfloat16* __restrict__ W,
                    const float* __restrict__ bias,
                    const float* __restrict__ res,
                    float* __restrict__ C)
{
    extern __shared__ __align__(16) char smem[];
    __nv_bfloat16* Abase = reinterpret_cast<__nv_bfloat16*>(smem);
    __nv_bfloat16* Bbase = Abase + 4 * G64A_ELEMS;

    const int N = D_MODEL, K = D_MODEL;
    const int bm = blockIdx.y, bn = blockIdx.x;

    const int tid = threadIdx.x;
    const int warp = tid >> 5, lane = tid & 31;
    const int wm = warp >> 1, wn = warp & 1;     // 2x2 warp grid, each 32x64
    const int gid = lane >> 2, tig = lane & 3;
    const int l15 = lane & 15, lhi = (lane >> 4) << 3;

    float acc[2][8][4];
    #pragma unroll
    for (int mt = 0; mt < 2; mt++)
        #pragma unroll
        for (int nt = 0; nt < 8; nt++)
            #pragma unroll
            for (int i = 0; i < 4; i++) acc[mt][nt][i] = 0.f;

    auto stage = [&](int s) {
        const int buf = s & 3;
        const int kt = s * 32;
        __nv_bfloat16* As = Abase + buf * G64A_ELEMS;
        __nv_bfloat16* Bs = Bbase + buf * G64B_ELEMS;
        #pragma unroll
        for (int i = 0; i < 2; i++) {       // A: 64x32 = 256 16B-chunks
            int idx = tid + i * 128;
            int r = idx >> 2, c = (idx & 3) * 8;
            cp16(As + r * 40 + c, A + (size_t)(bm * 64 + r) * K + kt + c);
        }
        #pragma unroll
        for (int i = 0; i < 4; i++) {       // B: 32x128 = 512 16B-chunks
            int idx = tid + i * 128;
            int r = idx >> 4, c = (idx & 15) * 8;
            cp16(Bs + r * 136 + c, W + (size_t)(kt + r) * N + bn * 128 + c);
        }
        cp_commit();
    };

    stage(0); stage(1); stage(2);

    for (int s = 0; s < GK_NSTG; s++) {
        cp_wait2();
        __syncthreads();
        if (s + 3 < GK_NSTG) stage(s + 3);
        else cp_commit();

        const int buf = s & 3;
        const __nv_bfloat16* As = Abase + buf * G64A_ELEMS;
        const __nv_bfloat16* Bs = Bbase + buf * G64B_ELEMS;

        #pragma unroll
        for (int kk = 0; kk < 32; kk += 16) {
            uint32_t aA[2][4];
            #pragma unroll
            for (int mt = 0; mt < 2; mt++)
                ldm_x4(aA[mt][0], aA[mt][1], aA[mt][2], aA[mt][3],
                       As + (wm * 32 + mt * 16 + l15) * 40 + kk + lhi);
            uint32_t bB[8][2];
            #pragma unroll
            for (int nh = 0; nh < 4; nh++) {
                uint32_t t0, t1, t2, t3;
                ldm_x4_t(t0, t1, t2, t3,
                         Bs + (kk + l15) * 136 + wn * 64 + nh * 16 + lhi);
                bB[2 * nh][0] = t0; bB[2 * nh][1] = t1;
                bB[2 * nh + 1][0] = t2; bB[2 * nh + 1][1] = t3;
            }
            #pragma unroll
            for (int mt = 0; mt < 2; mt++)
                #pragma unroll
                for (int nt = 0; nt < 8; nt++)
                    mma_bf16(acc[mt][nt], aA[mt], bB[nt]);
        }
    }

    #pragma unroll
    for (int mt = 0; mt < 2; mt++) {
        int row = bm * 64 + wm * 32 + mt * 16 + gid;
        #pragma unroll
        for (int nt = 0; nt < 8; nt++) {
            int col = bn * 128 + wn * 64 + nt * 8 + 2 * tig;
            float bb0 = bias[col], bb1 = bias[col + 1];
            size_t i0 = (size_t)row * N + col;
            size_t i1 = i0 + 8 * (size_t)N;
            float2 r0 = *reinterpret_cast<const float2*>(res + i0);
            float2 r1 = *reinterpret_cast<const float2*>(res + i1);
            *reinterpret_cast<float2*>(C + i0) =
                make_float2(acc[mt][nt][0] + bb0 + r0.x, acc[mt][nt][1] + bb1 + r0.y);
            *reinterpret_cast<float2*>(C + i1) =
                make_float2(acc[mt][nt][2] + bb0 + r1.x, acc[mt][nt][3] + bb1 + r1.y);
        }
    }
}

// ---------------------------------------------------------------------------
// Flash attention (round-16 best, with pacc folded into the PV loop):
// 128-row Q tile, 4 warps x two m16 row-groups, no-max bf16x2-ex2 softmax,
// l via ones-column tensor MMA, frame-0 shortcut, 2-buffer cp.async KV.
// ---------------------------------------------------------------------------
#define AT_QROWS   128
#define AT_SMEM    ((AT_QROWS * 72 + 2 * 64 * 72 + 2 * 64 * 72) * 2)  // 55296 B

__global__ __launch_bounds__(128)
void attn_kernel()
{
    extern __shared__ __align__(16) __nv_bfloat16 sm[];
    __nv_bfloat16* Qs = sm;                       // [128][72]
    __nv_bfloat16* Kb = sm + AT_QROWS * 72;       // [2][64][72]
    __nv_bfloat16* Vb = Kb + 2 * 64 * 72;         // [2][64][72]

    const int qt = blockIdx.x, h = blockIdx.y, bfi = blockIdx.z;
    const int bf0 = bfi & ~(N_FR - 1);
    const int nt_loop = ((bfi & (N_FR - 1)) == 0) ? 16 : 32;  // frame-0 shortcut
    const int tid = threadIdx.x;
    const int w = tid >> 5, lane = tid & 31;
    const int gid = lane >> 2, tig = lane & 3;
    const int l15 = lane & 15, lhi = (lane >> 4) << 3;

    // Stage Q tile, pre-scaled by 0.125 * log2(e)
    {
        const float qsc = 0.125f * 1.44269504f;
        #pragma unroll
        for (int i = 0; i < 8; i++) {
            int idx = tid + i * 128;
            int r = idx >> 3, c = (idx & 7) * 8;
            const __nv_bfloat16* p = g_q + (size_t)(bfi * SEQ + qt * AT_QROWS + r) * D_MODEL + h * HDIM + c;
            uint4 v = *reinterpret_cast<const uint4*>(p);
            __nv_bfloat16* pe = reinterpret_cast<__nv_bfloat16*>(&v);
            #pragma unroll
            for (int j = 0; j < 8; j++)
                pe[j] = __float2bfloat16_rn(__bfloat162float(pe[j]) * qsc);
            *reinterpret_cast<uint4*>(Qs + r * 72 + c) = v;
        }
    }

    auto stageKV = [&](int buf, int t) {
        const int sbf = (t < 16) ? bf0 : bfi;
        const int k0 = (t & 15) * 64;
        #pragma unroll
        for (int i = 0; i < 4; i++) {
            int idx = tid + i * 128;
            int r = idx >> 3, c = (idx & 7) * 8;
            size_t base = (size_t)(sbf * SEQ + k0 + r) * D_MODEL + h * HDIM + c;
            cp16(Kb + buf * 4608 + r * 72 + c, g_k + base);
            cp16(Vb + buf * 4608 + r * 72 + c, g_v + base);
        }
        cp_commit();
    };

    stageKV(0, 0);

    // Init V pad columns once (both buffers): col 64 = 1.0, cols 65..71 = 0.
    {
        int b = tid >> 6, r = tid & 63;
        __nv_bfloat16* row = Vb + b * 4608 + r * 72 + 64;
        row[0] = __float2bfloat16_rn(1.f);
        #pragma unroll
        for (int j = 1; j < 8; j++) row[j] = __float2bfloat16_rn(0.f);
    }
    __syncthreads();

    uint32_t qf[2][4][4];
    #pragma unroll
    for (int g = 0; g < 2; g++)
        #pragma unroll
        for (int kj = 0; kj < 4; kj++)
            ldm_x4(qf[g][kj][0], qf[g][kj][1], qf[g][kj][2], qf[g][kj][3],
                   Qs + (g * 64 + w * 16 + l15) * 72 + kj * 16 + lhi);

    uint32_t onesB[2];      // constant B fragment (col 64 = ones)
    ldm_x2_t(onesB[0], onesB[1], Vb + l15 * 72 + 64);

    float oacc[2][8][4];
    #pragma unroll
    for (int g = 0; g < 2; g++)
        #pragma unroll
        for (int nt = 0; nt < 8; nt++)
            #pragma unroll
            for (int i = 0; i < 4; i++) oacc[g][nt][i] = 0.f;
    float lacc[2][4];
    #pragma unroll
    for (int g = 0; g < 2; g++)
        #pragma unroll
        for (int i = 0; i < 4; i++) lacc[g][i] = 0.f;

    int buf = 0;
    for (int t = 0; t < nt_loop; t++) {
        cp_wait0();
        __syncthreads();
        if (t + 1 < nt_loop) stageKV(buf ^ 1, t + 1);

        // S = Q @ K^T (log2 units)
        float sacc[2][8][4];
        #pragma unroll
        for (int g = 0; g < 2; g++)
            #pragma unroll
            for (int nt = 0; nt < 8; nt++)
                #pragma unroll
                for (int i = 0; i < 4; i++) sacc[g][nt][i] = 0.f;

        #pragma unroll
        for (int ntp = 0; ntp < 4; ntp++) {
            #pragma unroll
            for (int kj = 0; kj < 4; kj++) {
                uint32_t t0, t1, t2, t3;
                ldm_x4(t0, t1, t2, t3, Kb + buf * 4608 + (ntp * 16 + l15) * 72 + kj * 16 + lhi);
                uint32_t be[2] = {t0, t2};
                uint32_t bo[2] = {t1, t3};
                #pragma unroll
                for (int g = 0; g < 2; g++) {
                    mma_bf16(sacc[g][2 * ntp],     qf[g][kj], be);
                    mma_bf16(sacc[g][2 * ntp + 1], qf[g][kj], bo);
                }
            }
        }

        // O += P @ V ; l += P @ ones.  P fragments computed in-loop
        // (ex2.approx.bf16x2 directly from sacc -> lower register liveness).
        #pragma unroll
        for (int kj = 0; kj < 4; kj++) {
            uint32_t ap[2][4];
            #pragma unroll
            for (int g = 0; g < 2; g++) {
                ap[g][0] = ex2_bf16x2(cvt_bf16x2(sacc[g][2 * kj][0],     sacc[g][2 * kj][1]));
                ap[g][1] = ex2_bf16x2(cvt_bf16x2(sacc[g][2 * kj][2],     sacc[g][2 * kj][3]));
                ap[g][2] = ex2_bf16x2(cvt_bf16x2(sacc[g][2 * kj + 1][0], sacc[g][2 * kj + 1][1]));
                ap[g][3] = ex2_bf16x2(cvt_bf16x2(sacc[g][2 * kj + 1][2], sacc[g][2 * kj + 1][3]));
            }
            int vrow = kj * 16 + ((lane >> 3) & 1) * 8 + (lane & 7);
            #pragma unroll
            for (int dp = 0; dp < 4; dp++) {
                int vcol = dp * 16 + ((lane >> 4) & 1) * 8;
                uint32_t b0, b1, b2, b3;
                ldm_x4_t(b0, b1, b2, b3, Vb + buf * 4608 + vrow * 72 + vcol);
                uint32_t bb0[2] = {b0, b1};
                uint32_t bb1[2] = {b2, b3};
                #pragma unroll
                for (int g = 0; g < 2; g++) {
                    mma_bf16(oacc[g][2 * dp],     ap[g], bb0);
                    mma_bf16(oacc[g][2 * dp + 1], ap[g], bb1);
                }
            }
            #pragma unroll
            for (int g = 0; g < 2; g++)
                mma_bf16(lacc[g], ap[g], onesB);
        }
        buf ^= 1;
    }

    #pragma unroll
    for (int g = 0; g < 2; g++) {
        float l0 = __shfl_sync(0xffffffffu, lacc[g][0], lane & 28);
        float l1 = __shfl_sync(0xffffffffu, lacc[g][2], lane & 28);
        const int r0 = g * 64 + w * 16 + gid;
        const float inv0 = 1.f / l0, inv1 = 1.f / l1;
        #pragma unroll
        for (int nt = 0; nt < 8; nt++) {
            int dcol = h * HDIM + nt * 8 + 2 * tig;
            size_t b0 = (size_t)(bfi * SEQ + qt * AT_QROWS + r0) * D_MODEL + dcol;
            size_t b1 = b0 + 8 * (size_t)D_MODEL;
            *reinterpret_cast<__nv_bfloat162*>(g_attn + b0) =
                __floats2bfloat162_rn(oacc[g][nt][0] * inv0, oacc[g][nt][1] * inv0);
            *reinterpret_cast<__nv_bfloat162*>(g_attn + b1) =
                __floats2bfloat162_rn(oacc[g][nt][2] * inv1, oacc[g][nt][3] * inv1);
        }
    }
}

// ---------------------------------------------------------------------------

extern "C" void kernel_launch(void* const* d_in, const int* in_sizes, int n_in,
                              void* d_out, int out_size)
{
    const float* hs = (const float*)d_in[0];
    const float* Wq = (const float*)d_in[1];
    const float* Wk = (const float*)d_in[2];
    const float* Wv = (const float*)d_in[3];
    const float* Wo = (const float*)d_in[4];
    const float* bq = (const float*)d_in[5];
    const float* bk = (const float*)d_in[6];
    const float* bv = (const float*)d_in[7];
    const float* bo = (const float*)d_in[8];
    float* out = (float*)d_out;

    __nv_bfloat16 *hsb, *wqb, *wkb, *wvb, *wob, *qp, *kp, *vp, *ap;
    cudaGetSymbolAddress((void**)&hsb, g_hs);
    cudaGetSymbolAddress((void**)&wqb, g_wq);
    cudaGetSymbolAddress((void**)&wkb, g_wk);
    cudaGetSymbolAddress((void**)&wvb, g_wv);
    cudaGetSymbolAddress((void**)&wob, g_wo);
    cudaGetSymbolAddress((void**)&qp, g_q);
    cudaGetSymbolAddress((void**)&kp, g_k);
    cudaGetSymbolAddress((void**)&vp, g_v);
    cudaGetSymbolAddress((void**)&ap, g_attn);

    const int n_hs = M_TOT * D_MODEL, n_w = D_MODEL * D_MODEL;
    cvt_kernel<<<n_hs / 4 / 256, 256>>>(hs, hsb, n_hs);
    cvt4_kernel<<<dim3(n_w / 4 / 256, 1, 4), 256>>>(Wq, Wk, Wv, Wo, wqb, wkb, wvb, wob, n_w);

    cudaFuncSetAttribute((const void*)gemm_qkv_kernel,
                         cudaFuncAttributeMaxDynamicSharedMemorySize, G_SMEM);
    cudaFuncSetAttribute((const void*)gemm_wo_kernel,
                         cudaFuncAttributeMaxDynamicSharedMemorySize, G64_SMEM);
    cudaFuncSetAttribute((const void*)attn_kernel,
                         cudaFuncAttributeMaxDynamicSharedMemorySize, AT_SMEM);

    // Fused QKV: grid.x = 30 (3 weights x 10 n-tiles of 128)
    gemm_qkv_kernel<<<dim3(30, M_TOT / 128), 128, G_SMEM>>>(
        hsb, wqb, wkb, wvb, bq, bk, bv, qp, kp, vp);

    attn_kernel<<<dim3(SEQ / AT_QROWS, N_HEADS, N_BF), 128, AT_SMEM>>>();

    // Wo: M64 tiles -> grid 10 x 128 = 1280 CTAs (2.9 waves, 3 CTAs/SM)
    gemm_wo_kernel<<<dim3(10, M_TOT / 64), 128, G64_SMEM>>>(ap, wob, bo, hs, out);
}